// round 8
// baseline (speedup 1.0000x reference)
#include <cuda_runtime.h>
#include <cstdint>

#define BATCH 32
#define NN    784
#define DD    512
#define RESO  28
#define KK    10
#define TI    8
#define NT    (NN / TI)         // 98 tiles per image
#define INF_VAL 100000.0f

// Normalized vectors + their sum-of-squares (rounded, matching reference).
__device__ float g_xn[(size_t)BATCH * NN * DD];
__device__ float g_sq[BATCH * NN];

// ---------- Kernel A: canary — unconditional full-output prefill (FLOAT) ----------
__global__ void canary_kernel(float* out) {
    const int e = blockIdx.x * 256 + threadIdx.x;
    if (e < BATCH * NN * KK) {
        const int row = e / KK;
        out[3 * e + 0] = (float)row;   // placeholder dst
        out[3 * e + 1] = (float)row;   // src (correct)
        out[3 * e + 2] = 0.0f;         // relation (correct)
    }
}

// ---------- Kernel B: exact-rounding normalize (warp per vector) ----------
__global__ void norm_kernel(const float* __restrict__ in) {
    const int vec  = blockIdx.x * 8 + (threadIdx.x >> 5);
    const int lane = threadIdx.x & 31;
    const float4* v = reinterpret_cast<const float4*>(in + (size_t)vec * DD);
    float4 a0 = v[lane], a1 = v[lane + 32], a2 = v[lane + 64], a3 = v[lane + 96];

    float s = 0.0f;
    s = fmaf(a0.x, a0.x, s); s = fmaf(a0.y, a0.y, s); s = fmaf(a0.z, a0.z, s); s = fmaf(a0.w, a0.w, s);
    s = fmaf(a1.x, a1.x, s); s = fmaf(a1.y, a1.y, s); s = fmaf(a1.z, a1.z, s); s = fmaf(a1.w, a1.w, s);
    s = fmaf(a2.x, a2.x, s); s = fmaf(a2.y, a2.y, s); s = fmaf(a2.z, a2.z, s); s = fmaf(a2.w, a2.w, s);
    s = fmaf(a3.x, a3.x, s); s = fmaf(a3.y, a3.y, s); s = fmaf(a3.z, a3.z, s); s = fmaf(a3.w, a3.w, s);
    #pragma unroll
    for (int off = 16; off > 0; off >>= 1)
        s = __fadd_rn(s, __shfl_xor_sync(0xffffffffu, s, off));

    const float nrm = fmaxf(__fsqrt_rn(s), 1e-12f);
    a0.x = __fdiv_rn(a0.x, nrm); a0.y = __fdiv_rn(a0.y, nrm);
    a0.z = __fdiv_rn(a0.z, nrm); a0.w = __fdiv_rn(a0.w, nrm);
    a1.x = __fdiv_rn(a1.x, nrm); a1.y = __fdiv_rn(a1.y, nrm);
    a1.z = __fdiv_rn(a1.z, nrm); a1.w = __fdiv_rn(a1.w, nrm);
    a2.x = __fdiv_rn(a2.x, nrm); a2.y = __fdiv_rn(a2.y, nrm);
    a2.z = __fdiv_rn(a2.z, nrm); a2.w = __fdiv_rn(a2.w, nrm);
    a3.x = __fdiv_rn(a3.x, nrm); a3.y = __fdiv_rn(a3.y, nrm);
    a3.z = __fdiv_rn(a3.z, nrm); a3.w = __fdiv_rn(a3.w, nrm);

    float s2 = 0.0f;
    s2 = fmaf(a0.x, a0.x, s2); s2 = fmaf(a0.y, a0.y, s2); s2 = fmaf(a0.z, a0.z, s2); s2 = fmaf(a0.w, a0.w, s2);
    s2 = fmaf(a1.x, a1.x, s2); s2 = fmaf(a1.y, a1.y, s2); s2 = fmaf(a1.z, a1.z, s2); s2 = fmaf(a1.w, a1.w, s2);
    s2 = fmaf(a2.x, a2.x, s2); s2 = fmaf(a2.y, a2.y, s2); s2 = fmaf(a2.z, a2.z, s2); s2 = fmaf(a2.w, a2.w, s2);
    s2 = fmaf(a3.x, a3.x, s2); s2 = fmaf(a3.y, a3.y, s2); s2 = fmaf(a3.z, a3.z, s2); s2 = fmaf(a3.w, a3.w, s2);
    #pragma unroll
    for (int off = 16; off > 0; off >>= 1)
        s2 = __fadd_rn(s2, __shfl_xor_sync(0xffffffffu, s2, off));

    float4* o = reinterpret_cast<float4*>(g_xn + (size_t)vec * DD);
    o[lane] = a0; o[lane + 32] = a1; o[lane + 64] = a2; o[lane + 96] = a3;
    if (lane == 0) g_sq[vec] = s2;
}

// ---------- Kernel C: fused distance + mask + top-K, 8-row tile ----------
__global__ void __launch_bounds__(256)
MediumRangeEdge_11072425689094_kernel(const float* __restrict__ rel,
                                      float* __restrict__ out) {
    __shared__ float s_xi[TI * DD];     // 16 KB (normalized rows)
    __shared__ float s_dist[TI * NN];   // 24.5 KB
    __shared__ float s_sqi[TI];

    const int blk  = blockIdx.x;
    const int b    = blk / NT;
    const int tile = blk - b * NT;
    const int i0   = tile * TI;
    const int tid  = threadIdx.x;
    const int lane = tid & 31;
    const int w    = tid >> 5;

    {   // stage normalized x_i rows (already rounded in g_xn)
        const float4* src4 = reinterpret_cast<const float4*>(g_xn + ((size_t)b * NN + i0) * DD);
        float4* dst4 = reinterpret_cast<float4*>(s_xi);
        #pragma unroll
        for (int t = 0; t < 4; ++t) dst4[tid + t * 256] = src4[tid + t * 256];
        if (tid < TI) s_sqi[tid] = g_sq[b * NN + i0 + tid];
    }
    __syncthreads();

    const int g  = lane >> 2;      // group in warp (0..7)
    const int lg = lane & 3;       // lane in group

    for (int j = w * 8 + g; j < NN; j += 64) {
        float acc[TI];
        #pragma unroll
        for (int r = 0; r < TI; ++r) acc[r] = 0.0f;

        const float4* xj = reinterpret_cast<const float4*>(g_xn + ((size_t)b * NN + j) * DD) + lg;

        #pragma unroll 4
        for (int c = 0; c < 32; ++c) {
            const float4 bv = xj[c * 4];
            #pragma unroll
            for (int r = 0; r < TI; ++r) {
                const float4 av = *reinterpret_cast<const float4*>(
                    s_xi + r * DD + c * 16 + lg * 4);
                acc[r] = fmaf(av.x, bv.x, fmaf(av.y, bv.y,
                         fmaf(av.z, bv.z, fmaf(av.w, bv.w, acc[r]))));
            }
        }
        #pragma unroll
        for (int r = 0; r < TI; ++r) {
            acc[r] = __fadd_rn(acc[r], __shfl_xor_sync(0xffffffffu, acc[r], 1));
            acc[r] = __fadd_rn(acc[r], __shfl_xor_sync(0xffffffffu, acc[r], 2));
        }

        const float sqj = g_sq[b * NN + j];
        const int rj = j / RESO, cj = j - rj * RESO;
        #pragma unroll
        for (int rr = 0; rr < 2; ++rr) {
            const int r = lg * 2 + rr;          // lane lg writes rows 2lg, 2lg+1
            const int irow = i0 + r;
            // reference order: ((sq_i + sq_j) - 2*dot) + rel  (+ INF*mask)
            float dv = __fsub_rn(__fadd_rn(s_sqi[r], sqj), __fmul_rn(2.0f, acc[r]));
            dv = __fadd_rn(dv, rel[(size_t)irow * NN + j]);
            const int ri = irow / RESO, ci = irow - ri * RESO;
            const int dr = ri - rj, dc = ci - cj;
            if (dr >= -1 && dr <= 1 && dc >= -1 && dc <= 1)
                dv = __fadd_rn(dv, INF_VAL);
            s_dist[r * NN + j] = dv;
        }
    }
    __syncthreads();

    // ---- top-K: 8 warps, one row each (exact top_k tie-breaking) ----
    {
        const float* drow = s_dist + w * NN;

        unsigned long long list[KK];
        #pragma unroll
        for (int q = 0; q < KK; ++q) list[q] = ~0ULL;

        for (int j = lane; j < NN; j += 32) {
            unsigned u = __float_as_uint(drow[j]);
            u = (u & 0x80000000u) ? ~u : (u | 0x80000000u);   // order-preserving
            const unsigned long long key = ((unsigned long long)u << 32) | (unsigned)j;
            if (key < list[KK - 1]) {
                list[KK - 1] = key;
                #pragma unroll
                for (int q = KK - 1; q > 0; --q) {
                    if (list[q] < list[q - 1]) {
                        const unsigned long long t = list[q - 1];
                        list[q - 1] = list[q];
                        list[q] = t;
                    }
                }
            }
        }

        const int row  = b * NN + i0 + w;
        const int base = row * (KK * 3);
        #pragma unroll
        for (int k = 0; k < KK; ++k) {
            unsigned long long v = list[0];
            #pragma unroll
            for (int off = 16; off > 0; off >>= 1) {
                const unsigned long long o = __shfl_xor_sync(0xffffffffu, v, off);
                if (o < v) v = o;
            }
            if (lane == k) {
                const int idx = (int)(v & 0xffffffffULL);
                out[base + 3 * k + 0] = (float)(idx + b * NN);  // dst  (FLOAT output)
                out[base + 3 * k + 1] = (float)row;             // src
                out[base + 3 * k + 2] = 0.0f;                   // relation
            }
            if (list[0] == v) {   // unique winner (key embeds j)
                #pragma unroll
                for (int q = 0; q < KK - 1; ++q) list[q] = list[q + 1];
                list[KK - 1] = ~0ULL;
            }
        }
    }
}

extern "C" void kernel_launch(void* const* d_in, const int* in_sizes, int n_in,
                              void* d_out, int out_size) {
    (void)out_size;
    const float* node_feature = (const float*)d_in[0];
    const float* relative_pos = (const float*)d_in[1];
    if (n_in >= 2 && in_sizes[0] < in_sizes[1]) {   // node_feature is the larger tensor
        node_feature = (const float*)d_in[1];
        relative_pos = (const float*)d_in[0];
    }
    float* out = (float*)d_out;

    canary_kernel<<<(BATCH * NN * KK + 255) / 256, 256>>>(out);
    norm_kernel<<<(BATCH * NN) / 8, 256>>>(node_feature);
    MediumRangeEdge_11072425689094_kernel<<<BATCH * NT, 256>>>(relative_pos, out);
}

// round 9
// speedup vs baseline: 1.2253x; 1.2253x over previous
#include <cuda_runtime.h>
#include <cstdint>

#define BATCH 32
#define NN    784
#define DD    512
#define RESO  28
#define KK    10
#define TI    16
#define NT    (NN / TI)         // 49 tiles per image
#define INF_VAL 100000.0f

// Normalized vectors + their sum-of-squares (rounded, matching reference).
__device__ float g_xn[(size_t)BATCH * NN * DD];
__device__ float g_sq[BATCH * NN];

// ---------- packed f32x2 helpers ----------
__device__ __forceinline__ unsigned long long fma2(unsigned long long a, unsigned long long b,
                                                   unsigned long long c) {
    unsigned long long d;
    asm("fma.rn.f32x2 %0, %1, %2, %3;" : "=l"(d) : "l"(a), "l"(b), "l"(c));
    return d;
}
__device__ __forceinline__ unsigned long long add2(unsigned long long a, unsigned long long b) {
    unsigned long long d;
    asm("add.rn.f32x2 %0, %1, %2;" : "=l"(d) : "l"(a), "l"(b));
    return d;
}
__device__ __forceinline__ void lds_v2u64(unsigned long long& a, unsigned long long& b,
                                          unsigned addr) {
    asm volatile("ld.shared.v2.u64 {%0,%1}, [%2];" : "=l"(a), "=l"(b) : "r"(addr));
}
__device__ __forceinline__ void ldg_v2u64(unsigned long long& a, unsigned long long& b,
                                          const void* p) {
    asm volatile("ld.global.nc.v2.u64 {%0,%1}, [%2];" : "=l"(a), "=l"(b) : "l"(p));
}
__device__ __forceinline__ float lo2(unsigned long long v) {
    return __uint_as_float((unsigned)(v & 0xffffffffULL));
}
__device__ __forceinline__ float hi2(unsigned long long v) {
    return __uint_as_float((unsigned)(v >> 32));
}
__device__ __forceinline__ unsigned long long shfl2(unsigned long long v, int m) {
    return __shfl_xor_sync(0xffffffffu, v, m);
}

// ---------- Kernel B: exact-rounding normalize (warp per vector) ----------
__global__ void norm_kernel(const float* __restrict__ in) {
    const int vec  = blockIdx.x * 8 + (threadIdx.x >> 5);
    const int lane = threadIdx.x & 31;
    const float4* v = reinterpret_cast<const float4*>(in + (size_t)vec * DD);
    float4 a0 = v[lane], a1 = v[lane + 32], a2 = v[lane + 64], a3 = v[lane + 96];

    float s = 0.0f;
    s = fmaf(a0.x, a0.x, s); s = fmaf(a0.y, a0.y, s); s = fmaf(a0.z, a0.z, s); s = fmaf(a0.w, a0.w, s);
    s = fmaf(a1.x, a1.x, s); s = fmaf(a1.y, a1.y, s); s = fmaf(a1.z, a1.z, s); s = fmaf(a1.w, a1.w, s);
    s = fmaf(a2.x, a2.x, s); s = fmaf(a2.y, a2.y, s); s = fmaf(a2.z, a2.z, s); s = fmaf(a2.w, a2.w, s);
    s = fmaf(a3.x, a3.x, s); s = fmaf(a3.y, a3.y, s); s = fmaf(a3.z, a3.z, s); s = fmaf(a3.w, a3.w, s);
    #pragma unroll
    for (int off = 16; off > 0; off >>= 1)
        s = __fadd_rn(s, __shfl_xor_sync(0xffffffffu, s, off));

    const float nrm = fmaxf(__fsqrt_rn(s), 1e-12f);
    a0.x = __fdiv_rn(a0.x, nrm); a0.y = __fdiv_rn(a0.y, nrm);
    a0.z = __fdiv_rn(a0.z, nrm); a0.w = __fdiv_rn(a0.w, nrm);
    a1.x = __fdiv_rn(a1.x, nrm); a1.y = __fdiv_rn(a1.y, nrm);
    a1.z = __fdiv_rn(a1.z, nrm); a1.w = __fdiv_rn(a1.w, nrm);
    a2.x = __fdiv_rn(a2.x, nrm); a2.y = __fdiv_rn(a2.y, nrm);
    a2.z = __fdiv_rn(a2.z, nrm); a2.w = __fdiv_rn(a2.w, nrm);
    a3.x = __fdiv_rn(a3.x, nrm); a3.y = __fdiv_rn(a3.y, nrm);
    a3.z = __fdiv_rn(a3.z, nrm); a3.w = __fdiv_rn(a3.w, nrm);

    float s2 = 0.0f;
    s2 = fmaf(a0.x, a0.x, s2); s2 = fmaf(a0.y, a0.y, s2); s2 = fmaf(a0.z, a0.z, s2); s2 = fmaf(a0.w, a0.w, s2);
    s2 = fmaf(a1.x, a1.x, s2); s2 = fmaf(a1.y, a1.y, s2); s2 = fmaf(a1.z, a1.z, s2); s2 = fmaf(a1.w, a1.w, s2);
    s2 = fmaf(a2.x, a2.x, s2); s2 = fmaf(a2.y, a2.y, s2); s2 = fmaf(a2.z, a2.z, s2); s2 = fmaf(a2.w, a2.w, s2);
    s2 = fmaf(a3.x, a3.x, s2); s2 = fmaf(a3.y, a3.y, s2); s2 = fmaf(a3.z, a3.z, s2); s2 = fmaf(a3.w, a3.w, s2);
    #pragma unroll
    for (int off = 16; off > 0; off >>= 1)
        s2 = __fadd_rn(s2, __shfl_xor_sync(0xffffffffu, s2, off));

    float4* o = reinterpret_cast<float4*>(g_xn + (size_t)vec * DD);
    o[lane] = a0; o[lane + 32] = a1; o[lane + 64] = a2; o[lane + 96] = a3;
    if (lane == 0) g_sq[vec] = s2;
}

// ---------- Kernel C: fused dist + mask + top-K. TI=16 rows, 2-col groups ----------
__global__ void __launch_bounds__(512)
MediumRangeEdge_11072425689094_kernel(const float* __restrict__ rel,
                                      float* __restrict__ out) {
    extern __shared__ float sh[];
    float* s_xi   = sh;              // TI*DD floats  (32 KB)
    float* s_dist = sh + TI * DD;    // TI*NN floats  (49 KB)
    __shared__ float s_sqi[TI];

    const int blk  = blockIdx.x;
    const int b    = blk / NT;
    const int tile = blk - b * NT;
    const int i0   = tile * TI;
    const int tid  = threadIdx.x;
    const int lane = tid & 31;
    const int w    = tid >> 5;

    {   // stage normalized x_i rows
        const float4* src4 = reinterpret_cast<const float4*>(g_xn + ((size_t)b * NN + i0) * DD);
        float4* dst4 = reinterpret_cast<float4*>(s_xi);
        #pragma unroll
        for (int t = 0; t < 4; ++t) dst4[tid + t * 512] = src4[tid + t * 512];
        if (tid < TI) s_sqi[tid] = g_sq[b * NN + i0 + tid];
    }
    __syncthreads();

    const int g   = lane >> 2;      // group in warp (0..7)
    const int lg  = lane & 3;       // lane in group
    const int gid = w * 8 + g;      // 0..127

    unsigned s_base;
    asm("{ .reg .u64 t; cvta.to.shared.u64 t, %1; cvt.u32.u64 %0, t; }"
        : "=r"(s_base) : "l"(s_xi));
    const unsigned s_lane = s_base + lg * 16;

    // ---- main: 3 passes of column-pairs (j0 = 256t + 2*gid, j1 = j0+1) ----
    for (int t = 0; t < 3; ++t) {
        const int j0 = t * 256 + 2 * gid;

        unsigned long long acc0[TI], acc1[TI];
        #pragma unroll
        for (int r = 0; r < TI; ++r) { acc0[r] = 0ULL; acc1[r] = 0ULL; }

        const char* xj0 = reinterpret_cast<const char*>(
            g_xn + ((size_t)b * NN + j0) * DD) + lg * 16;
        const char* xj1 = xj0 + DD * 4;

        #pragma unroll 4
        for (int c = 0; c < 32; ++c) {
            unsigned long long p0, p1, q0, q1;
            ldg_v2u64(p0, p1, xj0 + c * 64);
            ldg_v2u64(q0, q1, xj1 + c * 64);
            #pragma unroll
            for (int r = 0; r < TI; ++r) {
                unsigned long long a0, a1;
                lds_v2u64(a0, a1, s_lane + r * (DD * 4) + c * 64);
                acc0[r] = fma2(a0, p0, acc0[r]);
                acc0[r] = fma2(a1, p1, acc0[r]);
                acc1[r] = fma2(a0, q0, acc1[r]);
                acc1[r] = fma2(a1, q1, acc1[r]);
            }
        }

        #pragma unroll
        for (int r = 0; r < TI; ++r) {
            acc0[r] = add2(acc0[r], shfl2(acc0[r], 1));
            acc0[r] = add2(acc0[r], shfl2(acc0[r], 2));
            acc1[r] = add2(acc1[r], shfl2(acc1[r], 1));
            acc1[r] = add2(acc1[r], shfl2(acc1[r], 2));
        }

        const float sqj0 = g_sq[b * NN + j0];
        const float sqj1 = g_sq[b * NN + j0 + 1];
        const int rj0 = j0 / RESO, cj0 = j0 - rj0 * RESO;
        const int rj1 = (j0 + 1) / RESO, cj1 = (j0 + 1) - rj1 * RESO;
        #pragma unroll
        for (int rr = 0; rr < 4; ++rr) {
            const int r = lg * 4 + rr;          // lane lg writes rows 4lg..4lg+3
            const int irow = i0 + r;
            const int ri = irow / RESO, ci = irow - ri * RESO;
            const float* relrow = rel + (size_t)irow * NN;

            const float d0 = __fadd_rn(lo2(acc0[r]), hi2(acc0[r]));
            float dv0 = __fsub_rn(__fadd_rn(s_sqi[r], sqj0), __fmul_rn(2.0f, d0));
            dv0 = __fadd_rn(dv0, relrow[j0]);
            if (ri - rj0 >= -1 && ri - rj0 <= 1 && ci - cj0 >= -1 && ci - cj0 <= 1)
                dv0 = __fadd_rn(dv0, INF_VAL);
            s_dist[r * NN + j0] = dv0;

            const float d1 = __fadd_rn(lo2(acc1[r]), hi2(acc1[r]));
            float dv1 = __fsub_rn(__fadd_rn(s_sqi[r], sqj1), __fmul_rn(2.0f, d1));
            dv1 = __fadd_rn(dv1, relrow[j0 + 1]);
            if (ri - rj1 >= -1 && ri - rj1 <= 1 && ci - cj1 >= -1 && ci - cj1 <= 1)
                dv1 = __fadd_rn(dv1, INF_VAL);
            s_dist[r * NN + j0 + 1] = dv1;
        }
    }

    // ---- remainder: columns 768..783, one per group (gid < 16) ----
    if (gid < 16) {
        const int j = 768 + gid;
        unsigned long long acc[TI];
        #pragma unroll
        for (int r = 0; r < TI; ++r) acc[r] = 0ULL;

        const char* xj = reinterpret_cast<const char*>(
            g_xn + ((size_t)b * NN + j) * DD) + lg * 16;

        #pragma unroll 4
        for (int c = 0; c < 32; ++c) {
            unsigned long long p0, p1;
            ldg_v2u64(p0, p1, xj + c * 64);
            #pragma unroll
            for (int r = 0; r < TI; ++r) {
                unsigned long long a0, a1;
                lds_v2u64(a0, a1, s_lane + r * (DD * 4) + c * 64);
                acc[r] = fma2(a0, p0, acc[r]);
                acc[r] = fma2(a1, p1, acc[r]);
            }
        }
        #pragma unroll
        for (int r = 0; r < TI; ++r) {
            acc[r] = add2(acc[r], shfl2(acc[r], 1));
            acc[r] = add2(acc[r], shfl2(acc[r], 2));
        }

        const float sqj = g_sq[b * NN + j];
        const int rj = j / RESO, cj = j - rj * RESO;
        #pragma unroll
        for (int rr = 0; rr < 4; ++rr) {
            const int r = lg * 4 + rr;
            const int irow = i0 + r;
            const int ri = irow / RESO, ci = irow - ri * RESO;
            const float d = __fadd_rn(lo2(acc[r]), hi2(acc[r]));
            float dv = __fsub_rn(__fadd_rn(s_sqi[r], sqj), __fmul_rn(2.0f, d));
            dv = __fadd_rn(dv, rel[(size_t)irow * NN + j]);
            if (ri - rj >= -1 && ri - rj <= 1 && ci - cj >= -1 && ci - cj <= 1)
                dv = __fadd_rn(dv, INF_VAL);
            s_dist[r * NN + j] = dv;
        }
    }
    __syncthreads();

    // ---- top-K: 16 warps, one row each (exact top_k tie-breaking) ----
    {
        const float* drow = s_dist + w * NN;

        unsigned long long list[KK];
        #pragma unroll
        for (int q = 0; q < KK; ++q) list[q] = ~0ULL;

        for (int j = lane; j < NN; j += 32) {
            unsigned u = __float_as_uint(drow[j]);
            u = (u & 0x80000000u) ? ~u : (u | 0x80000000u);   // order-preserving
            const unsigned long long key = ((unsigned long long)u << 32) | (unsigned)j;
            if (key < list[KK - 1]) {
                list[KK - 1] = key;
                #pragma unroll
                for (int q = KK - 1; q > 0; --q) {
                    if (list[q] < list[q - 1]) {
                        const unsigned long long tkey = list[q - 1];
                        list[q - 1] = list[q];
                        list[q] = tkey;
                    }
                }
            }
        }

        const int row  = b * NN + i0 + w;
        const int base = row * (KK * 3);
        #pragma unroll
        for (int k = 0; k < KK; ++k) {
            unsigned long long v = list[0];
            #pragma unroll
            for (int off = 16; off > 0; off >>= 1) {
                const unsigned long long o = __shfl_xor_sync(0xffffffffu, v, off);
                if (o < v) v = o;
            }
            if (lane == k) {
                const int idx = (int)(v & 0xffffffffULL);
                out[base + 3 * k + 0] = (float)(idx + b * NN);  // dst (float output!)
                out[base + 3 * k + 1] = (float)row;             // src
                out[base + 3 * k + 2] = 0.0f;                   // relation
            }
            if (list[0] == v) {   // unique winner (key embeds j)
                #pragma unroll
                for (int q = 0; q < KK - 1; ++q) list[q] = list[q + 1];
                list[KK - 1] = ~0ULL;
            }
        }
    }
}

extern "C" void kernel_launch(void* const* d_in, const int* in_sizes, int n_in,
                              void* d_out, int out_size) {
    (void)out_size;
    const float* node_feature = (const float*)d_in[0];
    const float* relative_pos = (const float*)d_in[1];
    if (n_in >= 2 && in_sizes[0] < in_sizes[1]) {   // node_feature is the larger tensor
        node_feature = (const float*)d_in[1];
        relative_pos = (const float*)d_in[0];
    }
    float* out = (float*)d_out;

    norm_kernel<<<(BATCH * NN) / 8, 256>>>(node_feature);

    const int smem = (TI * DD + TI * NN) * (int)sizeof(float);   // 82944 B
    static int attr_done = 0;
    if (!attr_done) {
        cudaFuncSetAttribute(MediumRangeEdge_11072425689094_kernel,
                             cudaFuncAttributeMaxDynamicSharedMemorySize, smem);
        attr_done = 1;
    }
    MediumRangeEdge_11072425689094_kernel<<<BATCH * NT, 512, smem>>>(relative_pos, out);
}

// round 10
// speedup vs baseline: 3.6620x; 2.9886x over previous
#include <cuda_runtime.h>
#include <cstdint>

#define BATCH 32
#define NN    784
#define DD    512
#define RESO  28
#define KK    10
#define BT    112
#define NTB   7
#define NPAIR 28          // triangular tile pairs (p<=q)
#define NTHR  224         // 16 x 14 threads
#define KC    16          // k-chunk depth
#define SA_ST 116         // floats per k-row of A (112+4 pad)
#define SB_ST 58          // u64 per k-row of B (56+2 pad)
#define ST_ST 116         // transpose-tile stride (floats)
#define INF_VAL 100000.0f

typedef unsigned long long ull;

__device__ __align__(256) float g_xn[(size_t)BATCH * NN * DD];
__device__ __align__(256) float g_sq[BATCH * NN];
__device__ __align__(256) float g_dist[(size_t)BATCH * NN * NN];

__device__ __forceinline__ ull fma2(ull a, ull b, ull c) {
    ull d; asm("fma.rn.f32x2 %0,%1,%2,%3;" : "=l"(d) : "l"(a), "l"(b), "l"(c)); return d;
}
__device__ __forceinline__ ull dup2(float x) {
    ull d; asm("mov.b64 %0,{%1,%1};" : "=l"(d) : "f"(x)); return d;
}
__device__ __forceinline__ float lo2(ull v) { return __uint_as_float((unsigned)v); }
__device__ __forceinline__ float hi2(ull v) { return __uint_as_float((unsigned)(v >> 32)); }

// ---------- Kernel 1: exact-rounding normalize (warp per vector) ----------
__global__ void norm_kernel(const float* __restrict__ in) {
    const int vec  = blockIdx.x * 8 + (threadIdx.x >> 5);
    const int lane = threadIdx.x & 31;
    const float4* v = reinterpret_cast<const float4*>(in + (size_t)vec * DD);
    float4 a0 = v[lane], a1 = v[lane + 32], a2 = v[lane + 64], a3 = v[lane + 96];

    float s = 0.0f;
    s = fmaf(a0.x,a0.x,s); s = fmaf(a0.y,a0.y,s); s = fmaf(a0.z,a0.z,s); s = fmaf(a0.w,a0.w,s);
    s = fmaf(a1.x,a1.x,s); s = fmaf(a1.y,a1.y,s); s = fmaf(a1.z,a1.z,s); s = fmaf(a1.w,a1.w,s);
    s = fmaf(a2.x,a2.x,s); s = fmaf(a2.y,a2.y,s); s = fmaf(a2.z,a2.z,s); s = fmaf(a2.w,a2.w,s);
    s = fmaf(a3.x,a3.x,s); s = fmaf(a3.y,a3.y,s); s = fmaf(a3.z,a3.z,s); s = fmaf(a3.w,a3.w,s);
    #pragma unroll
    for (int off = 16; off > 0; off >>= 1)
        s = __fadd_rn(s, __shfl_xor_sync(0xffffffffu, s, off));

    const float nrm = fmaxf(__fsqrt_rn(s), 1e-12f);
    a0.x=__fdiv_rn(a0.x,nrm); a0.y=__fdiv_rn(a0.y,nrm); a0.z=__fdiv_rn(a0.z,nrm); a0.w=__fdiv_rn(a0.w,nrm);
    a1.x=__fdiv_rn(a1.x,nrm); a1.y=__fdiv_rn(a1.y,nrm); a1.z=__fdiv_rn(a1.z,nrm); a1.w=__fdiv_rn(a1.w,nrm);
    a2.x=__fdiv_rn(a2.x,nrm); a2.y=__fdiv_rn(a2.y,nrm); a2.z=__fdiv_rn(a2.z,nrm); a2.w=__fdiv_rn(a2.w,nrm);
    a3.x=__fdiv_rn(a3.x,nrm); a3.y=__fdiv_rn(a3.y,nrm); a3.z=__fdiv_rn(a3.z,nrm); a3.w=__fdiv_rn(a3.w,nrm);

    float s2 = 0.0f;
    s2 = fmaf(a0.x,a0.x,s2); s2 = fmaf(a0.y,a0.y,s2); s2 = fmaf(a0.z,a0.z,s2); s2 = fmaf(a0.w,a0.w,s2);
    s2 = fmaf(a1.x,a1.x,s2); s2 = fmaf(a1.y,a1.y,s2); s2 = fmaf(a1.z,a1.z,s2); s2 = fmaf(a1.w,a1.w,s2);
    s2 = fmaf(a2.x,a2.x,s2); s2 = fmaf(a2.y,a2.y,s2); s2 = fmaf(a2.z,a2.z,s2); s2 = fmaf(a2.w,a2.w,s2);
    s2 = fmaf(a3.x,a3.x,s2); s2 = fmaf(a3.y,a3.y,s2); s2 = fmaf(a3.z,a3.z,s2); s2 = fmaf(a3.w,a3.w,s2);
    #pragma unroll
    for (int off = 16; off > 0; off >>= 1)
        s2 = __fadd_rn(s2, __shfl_xor_sync(0xffffffffu, s2, off));

    float4* o = reinterpret_cast<float4*>(g_xn + (size_t)vec * DD);
    o[lane] = a0; o[lane + 32] = a1; o[lane + 64] = a2; o[lane + 96] = a3;
    if (lane == 0) g_sq[vec] = s2;
}

// ---------- Kernel 2: symmetric tiled GEMM -> dist (+rel+mask) into g_dist ----------
// Block: (batch, triangular tile pair p<=q), 112x112 tile, 224 threads (tx 0..15, ty 0..13).
// Thread tile: 7 rows (i = pbase+tx+16s) x 8 cols (j = qbase+8ty+cc), accs packed f32x2 over cols.
__global__ void __launch_bounds__(NTHR, 2)
MediumRangeEdge_11072425689094_kernel(const float* __restrict__ rel) {
    extern __shared__ char smraw[];
    float* sA0 = (float*)smraw;
    float* sA1 = (float*)(smraw + 7424);
    ull*   sB0 = (ull*)(smraw + 14848);
    ull*   sB1 = (ull*)(smraw + 22272);
    float* sT  = (float*)smraw;            // transpose tile (aliases buffers, used after)

    const int b = blockIdx.x / NPAIR;
    int rem = blockIdx.x - b * NPAIR;
    int p = 0, cnt = NTB;
    while (rem >= cnt) { rem -= cnt; --cnt; ++p; }
    const int q = p + rem;
    const int pbase = p * BT, qbase = q * BT;

    const int tid = threadIdx.x;
    const int tx  = tid & 15;
    const int ty  = tid >> 4;

    // staging assignment: idx -> (row, kquad)
    const int r0 = tid >> 2,          kq0 = tid & 3;
    const int r1 = (tid + NTHR) >> 2, kq1 = (tid + NTHR) & 3;

    const float4* gA = (const float4*)(g_xn + ((size_t)b * NN + pbase) * DD);
    const float4* gB = (const float4*)(g_xn + ((size_t)b * NN + qbase) * DD);

    float4 fa0 = gA[r0 * (DD/4) + kq0], fa1 = gA[r1 * (DD/4) + kq1];
    float4 fb0 = gB[r0 * (DD/4) + kq0], fb1 = gB[r1 * (DD/4) + kq1];

    ull acc[7][4];
    #pragma unroll
    for (int s = 0; s < 7; ++s)
        #pragma unroll
        for (int c = 0; c < 4; ++c) acc[s][c] = 0ULL;

    for (int kc = 0; kc < DD / KC; ++kc) {
        float* A  = (kc & 1) ? sA1 : sA0;
        ull*   Bq = (kc & 1) ? sB1 : sB0;
        float* Bf = (float*)Bq;

        // STS A: k-major scatter
        A[(4*kq0+0)*SA_ST + r0] = fa0.x;
        A[(4*kq0+1)*SA_ST + r0] = fa0.y;
        A[(4*kq0+2)*SA_ST + r0] = fa0.z;
        A[(4*kq0+3)*SA_ST + r0] = fa0.w;
        A[(4*kq1+0)*SA_ST + r1] = fa1.x;
        A[(4*kq1+1)*SA_ST + r1] = fa1.y;
        A[(4*kq1+2)*SA_ST + r1] = fa1.z;
        A[(4*kq1+3)*SA_ST + r1] = fa1.w;
        // STS B: column-pair packed f32x2
        {
            const int c2 = r0 >> 1, h = r0 & 1;
            Bf[((4*kq0+0)*SB_ST + c2)*2 + h] = fb0.x;
            Bf[((4*kq0+1)*SB_ST + c2)*2 + h] = fb0.y;
            Bf[((4*kq0+2)*SB_ST + c2)*2 + h] = fb0.z;
            Bf[((4*kq0+3)*SB_ST + c2)*2 + h] = fb0.w;
        }
        {
            const int c2 = r1 >> 1, h = r1 & 1;
            Bf[((4*kq1+0)*SB_ST + c2)*2 + h] = fb1.x;
            Bf[((4*kq1+1)*SB_ST + c2)*2 + h] = fb1.y;
            Bf[((4*kq1+2)*SB_ST + c2)*2 + h] = fb1.z;
            Bf[((4*kq1+3)*SB_ST + c2)*2 + h] = fb1.w;
        }
        __syncthreads();

        if (kc + 1 < DD / KC) {  // prefetch next chunk
            const int ko = (kc + 1) * (KC / 4);
            fa0 = gA[r0*(DD/4) + ko + kq0]; fa1 = gA[r1*(DD/4) + ko + kq1];
            fb0 = gB[r0*(DD/4) + ko + kq0]; fb1 = gB[r1*(DD/4) + ko + kq1];
        }

        const float* Ar = A + tx;
        const ull*   Br = Bq + 4 * ty;
        #pragma unroll
        for (int kk = 0; kk < KC; ++kk) {
            const ulonglong2 bb0 = *(const ulonglong2*)(Br + kk*SB_ST);
            const ulonglong2 bb1 = *(const ulonglong2*)(Br + kk*SB_ST + 2);
            #pragma unroll
            for (int s = 0; s < 7; ++s) {
                const ull av = dup2(Ar[kk*SA_ST + 16*s]);
                acc[s][0] = fma2(av, bb0.x, acc[s][0]);
                acc[s][1] = fma2(av, bb0.y, acc[s][1]);
                acc[s][2] = fma2(av, bb1.x, acc[s][2]);
                acc[s][3] = fma2(av, bb1.y, acc[s][3]);
            }
        }
    }
    __syncthreads();   // all warps done with buffers; sT may now alias them

    // ---- epilogue: dist = ((sq_i + sq_j) - 2*dot) + rel (+INF mask) ----
    float sqj[8]; int jr[8], jc[8];
    #pragma unroll
    for (int cc = 0; cc < 8; ++cc) {
        const int j = qbase + 8*ty + cc;
        sqj[cc] = g_sq[b*NN + j];
        jr[cc] = j / RESO; jc[cc] = j - jr[cc]*RESO;
    }
    #pragma unroll
    for (int s = 0; s < 7; ++s) {
        const int i  = pbase + tx + 16*s;
        const float sqi = g_sq[b*NN + i];
        const int ri = i / RESO, ci = i - ri*RESO;
        const float4 rl0 = *(const float4*)(rel + (size_t)i*NN + qbase + 8*ty);
        const float4 rl1 = *(const float4*)(rel + (size_t)i*NN + qbase + 8*ty + 4);
        const float rv[8] = {rl0.x, rl0.y, rl0.z, rl0.w, rl1.x, rl1.y, rl1.z, rl1.w};
        float ov[8];
        #pragma unroll
        for (int c = 0; c < 4; ++c) {
            const float d0 = lo2(acc[s][c]), d1 = hi2(acc[s][c]);
            float v0 = __fadd_rn(__fsub_rn(__fadd_rn(sqi, sqj[2*c]),
                                           __fmul_rn(2.0f, d0)), rv[2*c]);
            float v1 = __fadd_rn(__fsub_rn(__fadd_rn(sqi, sqj[2*c+1]),
                                           __fmul_rn(2.0f, d1)), rv[2*c+1]);
            int dr = ri - jr[2*c],   dc = ci - jc[2*c];
            if (dr >= -1 && dr <= 1 && dc >= -1 && dc <= 1) v0 = __fadd_rn(v0, INF_VAL);
            dr = ri - jr[2*c+1]; dc = ci - jc[2*c+1];
            if (dr >= -1 && dr <= 1 && dc >= -1 && dc <= 1) v1 = __fadd_rn(v1, INF_VAL);
            ov[2*c] = v0; ov[2*c+1] = v1;
        }
        float4* dst = (float4*)(g_dist + ((size_t)b*NN + i)*NN + qbase + 8*ty);
        dst[0] = make_float4(ov[0], ov[1], ov[2], ov[3]);
        dst[1] = make_float4(ov[4], ov[5], ov[6], ov[7]);
        if (p != q) {   // stash for transposed write
            #pragma unroll
            for (int cc = 0; cc < 8; ++cc)
                sT[(8*ty + cc)*ST_ST + tx + 16*s] = ov[cc];
        }
    }

    if (p != q) {   // symmetric write: dist[j][i] (rel/mask/sq symmetric)
        __syncthreads();
        const int jl = tid >> 1, hf = tid & 1;
        const float*  srow = sT + jl*ST_ST + hf*56;
        float* drow = g_dist + ((size_t)b*NN + qbase + jl)*NN + pbase + hf*56;
        #pragma unroll
        for (int m = 0; m < 14; ++m)
            ((float4*)drow)[m] = ((const float4*)srow)[m];
    }
}

// ---------- Kernel 3: top-K per row (warp per row), float outputs ----------
__global__ void __launch_bounds__(1024)
topk_kernel(float* __restrict__ out) {
    const int row  = blockIdx.x * 32 + (threadIdx.x >> 5);
    const int lane = threadIdx.x & 31;
    const float* drow = g_dist + (size_t)row * NN;

    ull list[KK];
    #pragma unroll
    for (int qq = 0; qq < KK; ++qq) list[qq] = ~0ULL;

    for (int j = lane; j < NN; j += 32) {
        unsigned u = __float_as_uint(drow[j]);
        u = (u & 0x80000000u) ? ~u : (u | 0x80000000u);     // order-preserving map
        const ull key = ((ull)u << 32) | (unsigned)j;
        if (key < list[KK-1]) {
            list[KK-1] = key;
            #pragma unroll
            for (int qq = KK-1; qq > 0; --qq)
                if (list[qq] < list[qq-1]) { const ull t = list[qq-1]; list[qq-1] = list[qq]; list[qq] = t; }
        }
    }

    const int bofs = (row / NN) * NN;
    const int base = row * (KK * 3);
    #pragma unroll
    for (int k = 0; k < KK; ++k) {
        ull v = list[0];
        #pragma unroll
        for (int off = 16; off > 0; off >>= 1) {
            const ull o = __shfl_xor_sync(0xffffffffu, v, off);
            if (o < v) v = o;
        }
        if (lane == k) {
            out[base + 3*k + 0] = (float)((int)(v & 0xffffffffULL) + bofs);  // dst
            out[base + 3*k + 1] = (float)row;                                // src
            out[base + 3*k + 2] = 0.0f;                                      // relation
        }
        if (list[0] == v) {
            #pragma unroll
            for (int qq = 0; qq < KK-1; ++qq) list[qq] = list[qq+1];
            list[KK-1] = ~0ULL;
        }
    }
}

extern "C" void kernel_launch(void* const* d_in, const int* in_sizes, int n_in,
                              void* d_out, int out_size) {
    (void)out_size;
    const float* node_feature = (const float*)d_in[0];
    const float* relative_pos = (const float*)d_in[1];
    if (n_in >= 2 && in_sizes[0] < in_sizes[1]) {
        node_feature = (const float*)d_in[1];
        relative_pos = (const float*)d_in[0];
    }
    float* out = (float*)d_out;

    const int smem = BT * ST_ST * (int)sizeof(float);   // 51968 B (> 4 staging buffers)
    static int attr_done = 0;
    if (!attr_done) {
        cudaFuncSetAttribute(MediumRangeEdge_11072425689094_kernel,
                             cudaFuncAttributeMaxDynamicSharedMemorySize, smem);
        attr_done = 1;
    }

    norm_kernel<<<(BATCH * NN) / 8, 256>>>(node_feature);
    MediumRangeEdge_11072425689094_kernel<<<BATCH * NPAIR, NTHR, smem>>>(relative_pos);
    topk_kernel<<<(BATCH * NN) / 32, 1024>>>(out);
}